// round 7
// baseline (speedup 1.0000x reference)
#include <cuda_runtime.h>
#include <cuda_bf16.h>
#include <math.h>
#include <cstdint>

#define N_ROWS 8192
#define DIM    512
#define MARGIN 0.5f

#define TM     128                     // CTA tile rows
#define TN     256                     // CTA tile cols
#define KC     64                      // K chunk (bf16)
#define NCHUNK (DIM / KC)              // 8
#define NBI    (N_ROWS / TM)           // 64
#define NBJ    (N_ROWS / TN)           // 32
#define NBLOCKS (NBJ * NBJ + NBJ)      // sum_{bj}(2bj+2) = 1056

#define PITCH  (KC * 2 + 16)           // 144 B pitch, ldmatrix conflict-free

__device__ __nv_bfloat16 g_Ebf[(size_t)N_ROWS * DIM];
__device__ double g_sum;

// ---------------------------------------------------------------------------
__device__ __forceinline__ uint32_t smem_u32(const void* p) {
    uint32_t a;
    asm("{ .reg .u64 t; cvta.to.shared.u64 t, %1; cvt.u32.u64 %0, t; }"
        : "=r"(a) : "l"(p));
    return a;
}
__device__ __forceinline__ void ldmx4(uint32_t* r, uint32_t addr) {
    asm volatile("ldmatrix.sync.aligned.m8n8.x4.shared.b16 {%0,%1,%2,%3}, [%4];"
                 : "=r"(r[0]), "=r"(r[1]), "=r"(r[2]), "=r"(r[3]) : "r"(addr));
}
__device__ __forceinline__ void mma16816(float* d, const uint32_t* a,
                                         uint32_t b0, uint32_t b1) {
    asm volatile(
        "mma.sync.aligned.m16n8k16.row.col.f32.bf16.bf16.f32 "
        "{%0,%1,%2,%3}, {%4,%5,%6,%7}, {%8,%9}, {%0,%1,%2,%3};"
        : "+f"(d[0]), "+f"(d[1]), "+f"(d[2]), "+f"(d[3])
        : "r"(a[0]), "r"(a[1]), "r"(a[2]), "r"(a[3]), "r"(b0), "r"(b1));
}
__device__ __forceinline__ void cp_async16(uint32_t smem_dst, const void* gmem_src) {
    asm volatile("cp.async.cg.shared.global [%0], [%1], 16;"
                 :: "r"(smem_dst), "l"(gmem_src) : "memory");
}
__device__ __forceinline__ void cp_commit() {
    asm volatile("cp.async.commit_group;" ::: "memory");
}
template <int N>
__device__ __forceinline__ void cp_wait() {
    asm volatile("cp.async.wait_group %0;" :: "n"(N) : "memory");
}

// ---------------------------------------------------------------------------
// Kernel 1: normalize + bf16 convert. Warp per row, 8 rows/block, no barrier.
// ---------------------------------------------------------------------------
__global__ void normalize_kernel(const float* __restrict__ emb) {
    const int wid  = threadIdx.x >> 5;
    const int lane = threadIdx.x & 31;
    const int row  = blockIdx.x * 8 + wid;
    if (row == 0 && lane == 0) g_sum = 0.0;   // ordered before loss_kernel

    const float4* src = reinterpret_cast<const float4*>(emb + (size_t)row * DIM);
    float4 v[4];
    float ss = 0.0f;
#pragma unroll
    for (int k = 0; k < 4; k++) {
        v[k] = src[lane + 32 * k];
        ss += v[k].x*v[k].x + v[k].y*v[k].y + v[k].z*v[k].z + v[k].w*v[k].w;
    }
    for (int off = 16; off > 0; off >>= 1)
        ss += __shfl_xor_sync(0xFFFFFFFF, ss, off);
    const float sc = 1.0f / fmaxf(sqrtf(ss), 1e-12f);

    uint2* dst = reinterpret_cast<uint2*>(g_Ebf + (size_t)row * DIM);
#pragma unroll
    for (int k = 0; k < 4; k++) {
        __nv_bfloat162 p0 = __floats2bfloat162_rn(v[k].x * sc, v[k].y * sc);
        __nv_bfloat162 p1 = __floats2bfloat162_rn(v[k].z * sc, v[k].w * sc);
        uint2 o;
        o.x = *reinterpret_cast<uint32_t*>(&p0);
        o.y = *reinterpret_cast<uint32_t*>(&p1);
        dst[lane + 32 * k] = o;
    }
}

// ---------------------------------------------------------------------------
// Kernel 2: 128x256 CTA tile, 8 warps (2x4), warp tile 64x64, cp.async x2.
// Upper-band tiles only; epilogue counts strict upper (gj>gi) pairs, x2.
// ---------------------------------------------------------------------------
#define SM_RLAB 0
#define SM_CLAB 512
#define SM_RED  1536
#define SM_BUF  1664
#define STAGE   ((TM + TN) * PITCH)        // 55296 B
#define SM_TOT  (SM_BUF + 2 * STAGE)       // 112256 B

__global__ __launch_bounds__(256, 1) void loss_kernel(const int* __restrict__ labels) {
    extern __shared__ char smem[];
    const uint32_t sbase = smem_u32(smem);
    const int tid  = threadIdx.x;
    const int wid  = tid >> 5;
    const int lane = tid & 31;
    const int wr   = wid >> 2;    // 0..1 : 64-row band
    const int wc   = wid & 3;     // 0..3 : 64-col band

    // decode blockIdx.x -> (bj, bi): tiles for col-block bj are [bj^2+bj, bj^2+3bj+2)
    const int idx = blockIdx.x;
    int bj = (int)((sqrtf(4.0f * idx + 1.0f) - 1.0f) * 0.5f);
    while (bj > 0 && bj * bj + bj > idx) bj--;
    while ((bj + 1) * (bj + 2) <= idx) bj++;
    const int bi = idx - (bj * bj + bj);

    const int rowBase = bi * TM;
    const int colBase = bj * TN;

    int* sRlab = reinterpret_cast<int*>(smem + SM_RLAB);
    int* sClab = reinterpret_cast<int*>(smem + SM_CLAB);
    if (tid < TM) sRlab[tid] = labels[rowBase + tid];
    sClab[tid] = labels[colBase + tid];

    // cp.async per-thread mapping: rA = tid>>3, g = tid&7
    // A rows rA+32p (p=0..3), B rows rA+32q (q=0..7)
    const int rA = tid >> 3;
    const int g  = tid & 7;
    const uint32_t dstA0 = (uint32_t)(rA * PITCH + g * 16);
    const uint32_t dstB0 = (uint32_t)(TM * PITCH + rA * PITCH + g * 16);
    const __nv_bfloat16* srcA0 = g_Ebf + (size_t)(rowBase + rA) * DIM + g * 8;
    const __nv_bfloat16* srcB0 = g_Ebf + (size_t)(colBase + rA) * DIM + g * 8;

    // ldmatrix per-lane bases (relative to stage base)
    const int lrow = lane & 15;
    const uint32_t khalf = (lane & 16) ? 16u : 0u;
    const uint32_t aRel = (uint32_t)(wr * 64 + lrow) * PITCH + khalf;
    const uint32_t bRel = (uint32_t)(TM * PITCH) + (uint32_t)(wc * 64 + lrow) * PITCH + khalf;

    float acc[4][8][4];
#pragma unroll
    for (int i = 0; i < 4; i++)
#pragma unroll
        for (int j = 0; j < 8; j++)
#pragma unroll
            for (int q = 0; q < 4; q++) acc[i][j][q] = 0.0f;

    // prefetch chunk 0 -> stage 0
    {
        const uint32_t st = sbase + SM_BUF;
#pragma unroll
        for (int p = 0; p < 4; p++)
            cp_async16(st + dstA0 + p * (32 * PITCH), srcA0 + (size_t)(32 * p) * DIM);
#pragma unroll
        for (int q = 0; q < 8; q++)
            cp_async16(st + dstB0 + q * (32 * PITCH), srcB0 + (size_t)(32 * q) * DIM);
        cp_commit();
    }

#pragma unroll 1
    for (int c = 0; c < NCHUNK; c++) {
        const uint32_t curBuf = sbase + SM_BUF + (uint32_t)((c & 1) * STAGE);

        if (c + 1 < NCHUNK) {
            const uint32_t nxtBuf = sbase + SM_BUF + (uint32_t)(((c + 1) & 1) * STAGE);
            const int koff = (c + 1) * KC;
#pragma unroll
            for (int p = 0; p < 4; p++)
                cp_async16(nxtBuf + dstA0 + p * (32 * PITCH),
                           srcA0 + (size_t)(32 * p) * DIM + koff);
#pragma unroll
            for (int q = 0; q < 8; q++)
                cp_async16(nxtBuf + dstB0 + q * (32 * PITCH),
                           srcB0 + (size_t)(32 * q) * DIM + koff);
            cp_commit();
            cp_wait<1>();
        } else {
            cp_wait<0>();
        }
        __syncthreads();

        const uint32_t aAddr = curBuf + aRel;
        const uint32_t bAddr = curBuf + bRel;
#pragma unroll
        for (int ks = 0; ks < KC / 16; ks++) {
            const uint32_t ko = ks * 32;  // bytes
            uint32_t a[4][4];
#pragma unroll
            for (int mi = 0; mi < 4; mi++)
                ldmx4(a[mi], aAddr + (uint32_t)(mi * 16) * PITCH + ko);
            uint32_t b[4][4];
#pragma unroll
            for (int nb = 0; nb < 4; nb++)
                ldmx4(b[nb], bAddr + (uint32_t)(nb * 16) * PITCH + ko);
#pragma unroll
            for (int mi = 0; mi < 4; mi++) {
#pragma unroll
                for (int ni = 0; ni < 8; ni++) {
                    const uint32_t b0 = b[ni >> 1][ni & 1];
                    const uint32_t b1 = b[ni >> 1][2 + (ni & 1)];
                    mma16816(acc[mi][ni], a[mi], b0, b1);
                }
            }
        }
        __syncthreads();
    }

    // ---- fused loss epilogue: strict upper triangle only, x2 ----
    float local = 0.0f;
#pragma unroll
    for (int mi = 0; mi < 4; mi++) {
        const int r0 = wr * 64 + mi * 16 + (lane >> 2);
#pragma unroll
        for (int ni = 0; ni < 8; ni++) {
            const int c0 = wc * 64 + ni * 8 + ((lane & 3) << 1);
#pragma unroll
            for (int h = 0; h < 2; h++) {
                const int ri = r0 + h * 8;
                const int gi = rowBase + ri;
                const int la = sRlab[ri];
#pragma unroll
                for (int q = 0; q < 2; q++) {
                    const int cj = c0 + q;
                    const int gj = colBase + cj;
                    if (gj > gi) {
                        const float s = acc[mi][ni][h * 2 + q];
                        float dd;
                        if (la == sClab[cj]) dd = 1.0f - s;
                        else                 dd = fmaxf(s - MARGIN, 0.0f);
                        local += dd * dd;
                    }
                }
            }
        }
    }
    local *= 2.0f;   // each strict-upper pair stands for (i,j) and (j,i)

    for (int off = 16; off > 0; off >>= 1)
        local += __shfl_xor_sync(0xFFFFFFFF, local, off);
    float* sRed = reinterpret_cast<float*>(smem + SM_RED);
    if (lane == 0) sRed[wid] = local;
    __syncthreads();
    if (tid == 0) {
        float t = 0.0f;
#pragma unroll
        for (int w = 0; w < 8; w++) t += sRed[w];
        atomicAdd(&g_sum, (double)t);
    }
}

// ---------------------------------------------------------------------------
__global__ void finalize_kernel(float* __restrict__ out) {
    const double num_pairs = (double)N_ROWS * (double)(N_ROWS - 1);
    out[0] = (float)(g_sum / num_pairs);
}

// ---------------------------------------------------------------------------
extern "C" void kernel_launch(void* const* d_in, const int* in_sizes, int n_in,
                              void* d_out, int out_size) {
    const float* embeddings = (const float*)d_in[0];
    const int*   labels     = (const int*)d_in[1];
    float*       out        = (float*)d_out;

    static bool attr_set = false;
    if (!attr_set) {
        cudaFuncSetAttribute(loss_kernel,
                             cudaFuncAttributeMaxDynamicSharedMemorySize, SM_TOT);
        attr_set = true;
    }

    normalize_kernel<<<N_ROWS / 8, 256>>>(embeddings);
    loss_kernel<<<NBLOCKS, 256, SM_TOT>>>(labels);
    finalize_kernel<<<1, 1>>>(out);
}

// round 8
// speedup vs baseline: 1.1112x; 1.1112x over previous
#include <cuda_runtime.h>
#include <cuda_fp16.h>
#include <math.h>
#include <cstdint>

#define N_ROWS 8192
#define DIM    512
#define MARGIN 0.5f

#define TILE   128
#define KC     64                      // K chunk (fp16 elems)
#define NCHUNK (DIM / KC)              // 8
#define NTILES (N_ROWS / TILE)         // 64
#define NBLOCKS (NTILES * (NTILES + 1) / 2)   // 2080

#define PITCH  (KC * 2 + 16)           // 144 B row pitch, ldmatrix conflict-free

// Scratch: normalized embeddings in fp16
__device__ __half g_Ehf[(size_t)N_ROWS * DIM];
__device__ double g_sum;

// ---------------------------------------------------------------------------
__device__ __forceinline__ uint32_t smem_u32(const void* p) {
    uint32_t a;
    asm("{ .reg .u64 t; cvta.to.shared.u64 t, %1; cvt.u32.u64 %0, t; }"
        : "=r"(a) : "l"(p));
    return a;
}
__device__ __forceinline__ void ldmx4(uint32_t* r, uint32_t addr) {
    asm volatile("ldmatrix.sync.aligned.m8n8.x4.shared.b16 {%0,%1,%2,%3}, [%4];"
                 : "=r"(r[0]), "=r"(r[1]), "=r"(r[2]), "=r"(r[3]) : "r"(addr));
}
// f16-accumulate MMA: D(f16x2 x2) += A(f16) * B(f16)
__device__ __forceinline__ void mma16816_f16(uint32_t* d, const uint32_t* a,
                                             uint32_t b0, uint32_t b1) {
    asm volatile(
        "mma.sync.aligned.m16n8k16.row.col.f16.f16.f16.f16 "
        "{%0,%1}, {%2,%3,%4,%5}, {%6,%7}, {%0,%1};"
        : "+r"(d[0]), "+r"(d[1])
        : "r"(a[0]), "r"(a[1]), "r"(a[2]), "r"(a[3]), "r"(b0), "r"(b1));
}
__device__ __forceinline__ void cp_async16(uint32_t smem_dst, const void* gmem_src) {
    asm volatile("cp.async.cg.shared.global [%0], [%1], 16;"
                 :: "r"(smem_dst), "l"(gmem_src) : "memory");
}
__device__ __forceinline__ void cp_commit() {
    asm volatile("cp.async.commit_group;" ::: "memory");
}
template <int N>
__device__ __forceinline__ void cp_wait() {
    asm volatile("cp.async.wait_group %0;" :: "n"(N) : "memory");
}

// ---------------------------------------------------------------------------
// Kernel 1: normalize + fp16 convert. Warp per row, 8 rows/block.
// ---------------------------------------------------------------------------
__global__ void normalize_kernel(const float* __restrict__ emb) {
    const int wid  = threadIdx.x >> 5;
    const int lane = threadIdx.x & 31;
    const int row  = blockIdx.x * 8 + wid;
    if (row == 0 && lane == 0) g_sum = 0.0;   // stream-ordered before loss_kernel

    const float4* src = reinterpret_cast<const float4*>(emb + (size_t)row * DIM);
    float4 v[4];
    float ss = 0.0f;
#pragma unroll
    for (int k = 0; k < 4; k++) {
        v[k] = src[lane + 32 * k];
        ss += v[k].x*v[k].x + v[k].y*v[k].y + v[k].z*v[k].z + v[k].w*v[k].w;
    }
    for (int off = 16; off > 0; off >>= 1)
        ss += __shfl_xor_sync(0xFFFFFFFF, ss, off);
    const float sc = 1.0f / fmaxf(sqrtf(ss), 1e-12f);

    uint2* dst = reinterpret_cast<uint2*>(g_Ehf + (size_t)row * DIM);
#pragma unroll
    for (int k = 0; k < 4; k++) {
        __half2 p0 = __floats2half2_rn(v[k].x * sc, v[k].y * sc);
        __half2 p1 = __floats2half2_rn(v[k].z * sc, v[k].w * sc);
        uint2 o;
        o.x = *reinterpret_cast<uint32_t*>(&p0);
        o.y = *reinterpret_cast<uint32_t*>(&p1);
        dst[lane + 32 * k] = o;
    }
}

// ---------------------------------------------------------------------------
// Kernel 2: mma.sync fp16 (f16-acc) sim-GEMM over upper triangle, fused loss.
// 128x128 CTA tile, 8 warps (2x4), warp tile 64x32, cp.async double buffer.
// ---------------------------------------------------------------------------
#define SM_RLAB 0
#define SM_CLAB 512
#define SM_RED  1024
#define SM_BUF  1088
#define BUFSZ   (2 * TILE * PITCH)     // A+B per stage: 36864 B
#define SM_TOT  (SM_BUF + 2 * BUFSZ)   // 74816 B

__global__ __launch_bounds__(256, 2) void loss_kernel(const int* __restrict__ labels) {
    extern __shared__ char smem[];
    const uint32_t sbase = smem_u32(smem);
    const int tid  = threadIdx.x;
    const int wid  = tid >> 5;
    const int lane = tid & 31;
    const int wr   = wid >> 2;    // 0..1 warp row
    const int wc   = wid & 3;     // 0..3 warp col

    // Triangular decode blockIdx.x -> (bi, bj), bj >= bi
    int idx = blockIdx.x;
    int bi = (int)((2.0f * NTILES + 1.0f
                    - sqrtf((2.0f*NTILES+1.0f)*(2.0f*NTILES+1.0f) - 8.0f*idx)) * 0.5f);
    while (bi > 0 && bi * NTILES - (bi * (bi - 1)) / 2 > idx) bi--;
    while ((bi + 1) * NTILES - ((bi + 1) * bi) / 2 <= idx) bi++;
    const int bj = bi + (idx - (bi * NTILES - (bi * (bi - 1)) / 2));

    const int rowBase = bi * TILE;
    const int colBase = bj * TILE;

    int* sRlab = reinterpret_cast<int*>(smem + SM_RLAB);
    int* sClab = reinterpret_cast<int*>(smem + SM_CLAB);
    if (tid < 128)       sRlab[tid]        = labels[rowBase + tid];
    else                 sClab[tid - 128]  = labels[colBase + (tid - 128)];

    // cp.async mapping: 8 x 16B per thread per chunk
    int cp_row[8]; int cp_isB[8]; int cp_g[8];
#pragma unroll
    for (int p = 0; p < 8; p++) {
        const int e = tid + p * 256;
        cp_isB[p] = e >> 10;
        cp_row[p] = (e & 1023) >> 3;
        cp_g[p]   = e & 7;
    }

    // ldmatrix per-lane bases (relative to buffer start)
    const int lrow = lane & 15;
    const uint32_t khalf = (lane & 16) ? 16u : 0u;
    const uint32_t aRel = (uint32_t)(wr * 64 + lrow) * PITCH + khalf;
    const uint32_t bRel = (uint32_t)(TILE * PITCH) + (uint32_t)(wc * 32 + lrow) * PITCH + khalf;

    // f16 accumulators: [mi][ni] -> 2 packed regs (row r0 / r0+8, 2 cols each)
    uint32_t acc[4][4][2];
#pragma unroll
    for (int i = 0; i < 4; i++)
#pragma unroll
        for (int j = 0; j < 4; j++) { acc[i][j][0] = 0u; acc[i][j][1] = 0u; }

    // ---- prefetch chunk 0 into buffer 0 ----
#pragma unroll
    for (int p = 0; p < 8; p++) {
        const int gro = (cp_isB[p] ? colBase : rowBase) + cp_row[p];
        const uint32_t dst = sbase + SM_BUF
            + (uint32_t)(cp_isB[p] * (TILE * PITCH) + cp_row[p] * PITCH + cp_g[p] * 16);
        cp_async16(dst, g_Ehf + (size_t)gro * DIM + cp_g[p] * 8);
    }
    cp_commit();

#pragma unroll 1
    for (int c = 0; c < NCHUNK; c++) {
        const uint32_t curBuf = sbase + SM_BUF + (uint32_t)((c & 1) * BUFSZ);

        if (c + 1 < NCHUNK) {
            const uint32_t nxtBuf = sbase + SM_BUF + (uint32_t)(((c + 1) & 1) * BUFSZ);
            const int koff = (c + 1) * KC;
#pragma unroll
            for (int p = 0; p < 8; p++) {
                const int gro = (cp_isB[p] ? colBase : rowBase) + cp_row[p];
                const uint32_t dst = nxtBuf
                    + (uint32_t)(cp_isB[p] * (TILE * PITCH) + cp_row[p] * PITCH + cp_g[p] * 16);
                cp_async16(dst, g_Ehf + (size_t)gro * DIM + koff + cp_g[p] * 8);
            }
            cp_commit();
            cp_wait<1>();
        } else {
            cp_wait<0>();
        }
        __syncthreads();

        const uint32_t aAddr = curBuf + aRel;
        const uint32_t bAddr = curBuf + bRel;
#pragma unroll
        for (int ks = 0; ks < KC / 16; ks++) {
            const uint32_t ko = ks * 32;  // bytes
            uint32_t a[4][4];
#pragma unroll
            for (int mi = 0; mi < 4; mi++)
                ldmx4(a[mi], aAddr + (uint32_t)(mi * 16) * PITCH + ko);
            uint32_t b[2][4];
#pragma unroll
            for (int nb = 0; nb < 2; nb++)
                ldmx4(b[nb], bAddr + (uint32_t)(nb * 16) * PITCH + ko);
#pragma unroll
            for (int mi = 0; mi < 4; mi++) {
#pragma unroll
                for (int ni = 0; ni < 4; ni++) {
                    const uint32_t b0 = b[ni >> 1][ni & 1];
                    const uint32_t b1 = b[ni >> 1][2 + (ni & 1)];
                    mma16816_f16(acc[mi][ni], a[mi], b0, b1);
                }
            }
        }
        __syncthreads();
    }

    // ---- fused loss epilogue on f16 register fragments ----
    float local = 0.0f;
#pragma unroll
    for (int mi = 0; mi < 4; mi++) {
        const int r0 = wr * 64 + mi * 16 + (lane >> 2);
#pragma unroll
        for (int ni = 0; ni < 4; ni++) {
            const int c0 = wc * 32 + ni * 8 + ((lane & 3) << 1);
#pragma unroll
            for (int h = 0; h < 2; h++) {
                const int ri = r0 + h * 8;
                const int gi = rowBase + ri;
                const int la = sRlab[ri];
                const __half2 hv = *reinterpret_cast<const __half2*>(&acc[mi][ni][h]);
                const float2 sv = __half22float2(hv);
#pragma unroll
                for (int q = 0; q < 2; q++) {
                    const int cj = c0 + q;
                    const int gj = colBase + cj;
                    if (gi == gj) continue;
                    const float s = (q == 0) ? sv.x : sv.y;
                    float dd;
                    if (la == sClab[cj]) dd = 1.0f - s;
                    else                 dd = fmaxf(s - MARGIN, 0.0f);
                    local += dd * dd;
                }
            }
        }
    }
    if (bi != bj) local *= 2.0f;   // symmetric tile counted twice

    // reduce: warp -> block -> global
    for (int off = 16; off > 0; off >>= 1)
        local += __shfl_xor_sync(0xFFFFFFFF, local, off);
    float* sRed = reinterpret_cast<float*>(smem + SM_RED);
    if (lane == 0) sRed[wid] = local;
    __syncthreads();
    if (tid == 0) {
        float t = 0.0f;
#pragma unroll
        for (int w = 0; w < 8; w++) t += sRed[w];
        atomicAdd(&g_sum, (double)t);
    }
}

// ---------------------------------------------------------------------------
__global__ void finalize_kernel(float* __restrict__ out) {
    const double num_pairs = (double)N_ROWS * (double)(N_ROWS - 1);
    out[0] = (float)(g_sum / num_pairs);
}

// ---------------------------------------------------------------------------
extern "C" void kernel_launch(void* const* d_in, const int* in_sizes, int n_in,
                              void* d_out, int out_size) {
    const float* embeddings = (const float*)d_in[0];
    const int*   labels     = (const int*)d_in[1];
    float*       out        = (float*)d_out;

    static bool attr_set = false;
    if (!attr_set) {
        cudaFuncSetAttribute(loss_kernel,
                             cudaFuncAttributeMaxDynamicSharedMemorySize, SM_TOT);
        attr_set = true;
    }

    normalize_kernel<<<N_ROWS / 8, 256>>>(embeddings);
    loss_kernel<<<NBLOCKS, 256, SM_TOT>>>(labels);
    finalize_kernel<<<1, 1>>>(out);
}

// round 10
// speedup vs baseline: 1.2184x; 1.0964x over previous
#include <cuda_runtime.h>
#include <cuda_fp16.h>
#include <math.h>
#include <cstdint>

#define N_ROWS 8192
#define DIM    512
#define MARGIN 0.5f

#define TILE   128
#define KC     64                      // K chunk (fp16 elems)
#define NCHUNK (DIM / KC)              // 8
#define NTILES (N_ROWS / TILE)         // 64
#define NBLOCKS (NTILES * (NTILES + 1) / 2)   // 2080

#define PITCH  (KC * 2 + 16)           // 144 B row pitch, ldmatrix conflict-free

// Scratch: normalized embeddings in fp16
__device__ __half g_Ehf[(size_t)N_ROWS * DIM];
__device__ double g_sum;

// ---------------------------------------------------------------------------
__device__ __forceinline__ uint32_t smem_u32(const void* p) {
    uint32_t a;
    asm("{ .reg .u64 t; cvta.to.shared.u64 t, %1; cvt.u32.u64 %0, t; }"
        : "=r"(a) : "l"(p));
    return a;
}
__device__ __forceinline__ void ldmx4(uint32_t* r, uint32_t addr) {
    asm volatile("ldmatrix.sync.aligned.m8n8.x4.shared.b16 {%0,%1,%2,%3}, [%4];"
                 : "=r"(r[0]), "=r"(r[1]), "=r"(r[2]), "=r"(r[3]) : "r"(addr));
}
// f16-accumulate MMA
__device__ __forceinline__ void mma16816_f16(uint32_t* d, const uint32_t* a,
                                             uint32_t b0, uint32_t b1) {
    asm volatile(
        "mma.sync.aligned.m16n8k16.row.col.f16.f16.f16.f16 "
        "{%0,%1}, {%2,%3,%4,%5}, {%6,%7}, {%0,%1};"
        : "+r"(d[0]), "+r"(d[1])
        : "r"(a[0]), "r"(a[1]), "r"(a[2]), "r"(a[3]), "r"(b0), "r"(b1));
}
__device__ __forceinline__ void cp_async16(uint32_t smem_dst, const void* gmem_src) {
    asm volatile("cp.async.cg.shared.global [%0], [%1], 16;"
                 :: "r"(smem_dst), "l"(gmem_src) : "memory");
}
__device__ __forceinline__ void cp_commit() {
    asm volatile("cp.async.commit_group;" ::: "memory");
}
template <int N>
__device__ __forceinline__ void cp_wait() {
    asm volatile("cp.async.wait_group %0;" :: "n"(N) : "memory");
}

// ---------------------------------------------------------------------------
// Kernel 1: normalize + fp16 convert. Warp per row, 8 rows/block.
// ---------------------------------------------------------------------------
__global__ void normalize_kernel(const float* __restrict__ emb) {
    const int wid  = threadIdx.x >> 5;
    const int lane = threadIdx.x & 31;
    const int row  = blockIdx.x * 8 + wid;
    if (row == 0 && lane == 0) g_sum = 0.0;   // stream-ordered before loss_kernel

    const float4* src = reinterpret_cast<const float4*>(emb + (size_t)row * DIM);
    float4 v[4];
    float ss = 0.0f;
#pragma unroll
    for (int k = 0; k < 4; k++) {
        v[k] = src[lane + 32 * k];
        ss += v[k].x*v[k].x + v[k].y*v[k].y + v[k].z*v[k].z + v[k].w*v[k].w;
    }
    for (int off = 16; off > 0; off >>= 1)
        ss += __shfl_xor_sync(0xFFFFFFFF, ss, off);
    const float sc = 1.0f / fmaxf(sqrtf(ss), 1e-12f);

    uint2* dst = reinterpret_cast<uint2*>(g_Ehf + (size_t)row * DIM);
#pragma unroll
    for (int k = 0; k < 4; k++) {
        __half2 p0 = __floats2half2_rn(v[k].x * sc, v[k].y * sc);
        __half2 p1 = __floats2half2_rn(v[k].z * sc, v[k].w * sc);
        uint2 o;
        o.x = *reinterpret_cast<uint32_t*>(&p0);
        o.y = *reinterpret_cast<uint32_t*>(&p1);
        dst[lane + 32 * k] = o;
    }
}

// ---------------------------------------------------------------------------
// Kernel 2: fp16 (f16-acc) sim-GEMM, upper triangle, fused loss.
// 128x128 CTA tile, 4 warps (2x2), warp tile 64x64, cp.async double buffer.
// ---------------------------------------------------------------------------
#define SM_RLAB 0
#define SM_CLAB 512
#define SM_RED  1024
#define SM_BUF  1088
#define BUFSZ   (2 * TILE * PITCH)     // A+B per stage: 36864 B
#define SM_TOT  (SM_BUF + 2 * BUFSZ)   // 74816 B

__global__ __launch_bounds__(128, 2) void loss_kernel(const int* __restrict__ labels) {
    extern __shared__ char smem[];
    const uint32_t sbase = smem_u32(smem);
    const int tid  = threadIdx.x;      // 0..127
    const int wid  = tid >> 5;         // 0..3
    const int lane = tid & 31;
    const int wr   = wid >> 1;    // 0..1 : 64-row band
    const int wc   = wid & 1;     // 0..1 : 64-col band

    // Triangular decode blockIdx.x -> (bi, bj), bj >= bi
    int idx = blockIdx.x;
    int bi = (int)((2.0f * NTILES + 1.0f
                    - sqrtf((2.0f*NTILES+1.0f)*(2.0f*NTILES+1.0f) - 8.0f*idx)) * 0.5f);
    while (bi > 0 && bi * NTILES - (bi * (bi - 1)) / 2 > idx) bi--;
    while ((bi + 1) * NTILES - ((bi + 1) * bi) / 2 <= idx) bi++;
    const int bj = bi + (idx - (bi * NTILES - (bi * (bi - 1)) / 2));

    const int rowBase = bi * TILE;
    const int colBase = bj * TILE;

    int* sRlab = reinterpret_cast<int*>(smem + SM_RLAB);
    int* sClab = reinterpret_cast<int*>(smem + SM_CLAB);
    sRlab[tid] = labels[rowBase + tid];
    sClab[tid] = labels[colBase + tid];

    // cp.async mapping: 16 x 16B per thread per chunk (2048 total)
    int cp_row[16]; int cp_isB[16]; int cp_g[16];
#pragma unroll
    for (int p = 0; p < 16; p++) {
        const int e = tid + p * 128;
        cp_isB[p] = e >> 10;
        cp_row[p] = (e & 1023) >> 3;
        cp_g[p]   = e & 7;
    }

    // ldmatrix per-lane bases (relative to buffer start)
    const int lrow = lane & 15;
    const uint32_t khalf = (lane & 16) ? 16u : 0u;
    const uint32_t aRel = (uint32_t)(wr * 64 + lrow) * PITCH + khalf;
    const uint32_t bRel = (uint32_t)(TILE * PITCH) + (uint32_t)(wc * 64 + lrow) * PITCH + khalf;

    // f16 accumulators: [mi][ni] -> 2 packed regs
    uint32_t acc[4][8][2];
#pragma unroll
    for (int i = 0; i < 4; i++)
#pragma unroll
        for (int j = 0; j < 8; j++) { acc[i][j][0] = 0u; acc[i][j][1] = 0u; }

    // ---- prefetch chunk 0 into buffer 0 ----
#pragma unroll
    for (int p = 0; p < 16; p++) {
        const int gro = (cp_isB[p] ? colBase : rowBase) + cp_row[p];
        const uint32_t dst = sbase + SM_BUF
            + (uint32_t)(cp_isB[p] * (TILE * PITCH) + cp_row[p] * PITCH + cp_g[p] * 16);
        cp_async16(dst, g_Ehf + (size_t)gro * DIM + cp_g[p] * 8);
    }
    cp_commit();

#pragma unroll 1
    for (int c = 0; c < NCHUNK; c++) {
        const uint32_t curBuf = sbase + SM_BUF + (uint32_t)((c & 1) * BUFSZ);

        if (c + 1 < NCHUNK) {
            const uint32_t nxtBuf = sbase + SM_BUF + (uint32_t)(((c + 1) & 1) * BUFSZ);
            const int koff = (c + 1) * KC;
#pragma unroll
            for (int p = 0; p < 16; p++) {
                const int gro = (cp_isB[p] ? colBase : rowBase) + cp_row[p];
                const uint32_t dst = nxtBuf
                    + (uint32_t)(cp_isB[p] * (TILE * PITCH) + cp_row[p] * PITCH + cp_g[p] * 16);
                cp_async16(dst, g_Ehf + (size_t)gro * DIM + koff + cp_g[p] * 8);
            }
            cp_commit();
            cp_wait<1>();
        } else {
            cp_wait<0>();
        }
        __syncthreads();

        const uint32_t aAddr = curBuf + aRel;
        const uint32_t bAddr = curBuf + bRel;
#pragma unroll
        for (int ks = 0; ks < KC / 16; ks++) {
            const uint32_t ko = ks * 32;  // bytes
            uint32_t a[4][4];
#pragma unroll
            for (int mi = 0; mi < 4; mi++)
                ldmx4(a[mi], aAddr + (uint32_t)(mi * 16) * PITCH + ko);
            uint32_t b[4][4];
#pragma unroll
            for (int nb = 0; nb < 4; nb++)
                ldmx4(b[nb], bAddr + (uint32_t)(nb * 16) * PITCH + ko);
#pragma unroll
            for (int mi = 0; mi < 4; mi++) {
#pragma unroll
                for (int ni = 0; ni < 8; ni++) {
                    const uint32_t b0 = b[ni >> 1][ni & 1];
                    const uint32_t b1 = b[ni >> 1][2 + (ni & 1)];
                    mma16816_f16(acc[mi][ni], a[mi], b0, b1);
                }
            }
        }
        __syncthreads();
    }

    // ---- fused loss epilogue on f16 register fragments ----
    float local = 0.0f;
#pragma unroll
    for (int mi = 0; mi < 4; mi++) {
        const int r0 = wr * 64 + mi * 16 + (lane >> 2);
#pragma unroll
        for (int ni = 0; ni < 8; ni++) {
            const int c0 = wc * 64 + ni * 8 + ((lane & 3) << 1);
#pragma unroll
            for (int h = 0; h < 2; h++) {
                const int ri = r0 + h * 8;
                const int gi = rowBase + ri;
                const int la = sRlab[ri];
                const __half2 hv = *reinterpret_cast<const __half2*>(&acc[mi][ni][h]);
                const float2 sv = __half22float2(hv);
#pragma unroll
                for (int q = 0; q < 2; q++) {
                    const int cj = c0 + q;
                    const int gj = colBase + cj;
                    if (gi == gj) continue;
                    const float s = (q == 0) ? sv.x : sv.y;
                    float dd;
                    if (la == sClab[cj]) dd = 1.0f - s;
                    else                 dd = fmaxf(s - MARGIN, 0.0f);
                    local += dd * dd;
                }
            }
        }
    }
    if (bi != bj) local *= 2.0f;   // symmetric tile counted twice

    // reduce: warp -> block -> global
    for (int off = 16; off > 0; off >>= 1)
        local += __shfl_xor_sync(0xFFFFFFFF, local, off);
    float* sRed = reinterpret_cast<float*>(smem + SM_RED);
    if (lane == 0) sRed[wid] = local;
    __syncthreads();
    if (tid == 0) {
        float t = sRed[0] + sRed[1] + sRed[2] + sRed[3];
        atomicAdd(&g_sum, (double)t);
    }
}

// ---------------------------------------------------------------------------
__global__ void finalize_kernel(float* __restrict__ out) {
    const double num_pairs = (double)N_ROWS * (double)(N_ROWS - 1);
    out[0] = (float)(g_sum / num_pairs);
}

// ---------------------------------------------------------------------------
extern "C" void kernel_launch(void* const* d_in, const int* in_sizes, int n_in,
                              void* d_out, int out_size) {
    const float* embeddings = (const float*)d_in[0];
    const int*   labels     = (const int*)d_in[1];
    float*       out        = (float*)d_out;

    static bool attr_set = false;
    if (!attr_set) {
        cudaFuncSetAttribute(loss_kernel,
                             cudaFuncAttributeMaxDynamicSharedMemorySize, SM_TOT);
        attr_set = true;
    }

    normalize_kernel<<<N_ROWS / 8, 256>>>(embeddings);
    loss_kernel<<<NBLOCKS, 128, SM_TOT>>>(labels);
    finalize_kernel<<<1, 1>>>(out);
}